// round 9
// baseline (speedup 1.0000x reference)
#include <cuda_runtime.h>
#include <math.h>

typedef unsigned long long u64;

// Problem constants
#define B_  10
#define T_  2048
#define I_  128
#define H_  256
#define L_  6
#define G4  (4 * H_)      // 1024 gate rows per layer

// Kernel config
#define NBLK     24        // blocks per layer (6*24 = 144 <= 148 SMs, co-resident)
#define THREADS  448
#define ROWS_MAX 44        // 4 * ceil(256/24)
#define JC_MAX   11
#define KCH      32        // per-thread k-chunk per half (input & recurrent)
#define PS       17        // psum stride: 16 slots (8 input + 8 rec) + pad
#define KSTRIDE  520       // vbuf row stride (floats)
#define GEMM_T   352       // 8 kc * 44 rr
#define CELL0    192       // cell threads: 192..319 (warps 6-9)

// Scratch (device globals: allocation-free contract)
__device__ float g_hseq[(size_t)L_ * (T_ + 1) * B_ * H_];
__device__ int   g_prog[L_ * NBLK * 32];   // per-block progress, 128B padded

__global__ void lstm_init_kernel(const float* __restrict__ h0) {
    int tid = blockIdx.x * blockDim.x + threadIdx.x;
    if (tid < L_ * B_ * H_) {
        int l = tid / (B_ * H_);
        int rem = tid - l * (B_ * H_);
        g_hseq[((size_t)l * (T_ + 1)) * B_ * H_ + rem] = h0[tid];
    }
    if (tid < L_ * NBLK * 32) {
        g_prog[tid] = 0;
    }
}

__device__ __forceinline__ float tanh_approx(float x) {
    float y;
    asm("tanh.approx.f32 %0, %1;" : "=f"(y) : "f"(x));
    return y;
}

__device__ __forceinline__ int ld_acq(const int* p) {
    int v;
    asm volatile("ld.acquire.gpu.global.b32 %0, [%1];" : "=r"(v) : "l"(p));
    return v;
}

__global__ void __launch_bounds__(THREADS, 1)
lstm_pipeline_kernel(const float* __restrict__ x,
                     const float* __restrict__ c0,
                     const float* __restrict__ Wih0,
                     const float* __restrict__ Wih,   // [L-1][4H][H]
                     const float* __restrict__ Whh,   // [L][4H][H]
                     const float* __restrict__ bih,   // [L][4H]
                     const float* __restrict__ bhh,   // [L][4H]
                     float* __restrict__ out)         // [L][B][H]
{
    __shared__ float vbuf[B_ * KSTRIDE];               // [input | h_prev]
    __shared__ float psum[ROWS_MAX * B_ * PS];         // partials, 16 slots + pad
    __shared__ float csm[JC_MAX * B_];
    __shared__ float bsm[ROWS_MAX];

    const int l     = blockIdx.x / NBLK;
    const int p     = blockIdx.x % NBLK;
    const int jbase = (p * H_) / NBLK;
    const int jend  = ((p + 1) * H_) / NBLK;
    const int jc    = jend - jbase;     // 10 or 11
    const int rows  = 4 * jc;           // gate rows owned by this block
    const int KIN   = (l == 0) ? I_ : H_;
    const int nkcin = KIN / KCH;        // input k-chunks: 4 or 8
    const int tid   = threadIdx.x;
    const int wid   = tid >> 5;
    const int jcB   = jc * B_;

    // ---- GEMM task: thread = (kc, rr); rr fastest so warps share kc ----
    const int rr = tid % ROWS_MAX;
    const int kc = tid / ROWS_MAX;       // 0..7 for tid < 352
    const bool row_ok     = (tid < GEMM_T) && (rr < rows);
    const bool in_active  = row_ok && (kc < nkcin);
    const bool rec_active = row_ok;      // rec half always has 8 chunks

    // ---- weights: 32 input floats + 32 recurrent floats per thread ----
    u64 wi[16], wr[16];
    {
        const int gate = rr / jc;
        const int jl   = rr - gate * jc;
        const int g    = gate * H_ + jbase + jl;
        if (in_active) {
            const float* wp = (l == 0)
                ? (Wih0 + (size_t)g * I_ + kc * KCH)
                : (Wih + ((size_t)(l - 1) * G4 + g) * H_ + kc * KCH);
            const ulonglong2* src = (const ulonglong2*)wp;
            #pragma unroll
            for (int i = 0; i < 8; i++) {
                ulonglong2 w = src[i];
                wi[2 * i] = w.x; wi[2 * i + 1] = w.y;
            }
        } else {
            #pragma unroll
            for (int i = 0; i < 16; i++) wi[i] = 0ULL;
        }
        if (rec_active) {
            const ulonglong2* src =
                (const ulonglong2*)(Whh + ((size_t)l * G4 + g) * H_ + kc * KCH);
            #pragma unroll
            for (int i = 0; i < 8; i++) {
                ulonglong2 w = src[i];
                wr[2 * i] = w.x; wr[2 * i + 1] = w.y;
            }
        } else {
            #pragma unroll
            for (int i = 0; i < 16; i++) wr[i] = 0ULL;
        }
    }

    // ---- biases, initial cell state, psum zero-fill ----
    for (int r = tid; r < rows; r += THREADS) {
        int gate = r / jc;
        int jl   = r - gate * jc;
        int g    = gate * H_ + jbase + jl;
        bsm[r] = bih[l * G4 + g] + bhh[l * G4 + g];
    }
    for (int e = tid; e < jcB; e += THREADS) {
        int jl = e / B_;
        int b  = e - jl * B_;
        csm[e] = c0[((size_t)l * B_ + b) * H_ + jbase + jl];
    }
    for (int e = tid; e < ROWS_MAX * B_ * PS; e += THREADS) {
        psum[e] = 0.f;
    }
    // pre-loop: verify lower-layer flags for t=0
    if (l > 0 && wid == 12 && (tid & 31) < NBLK) {
        const int* f = &g_prog[((l - 1) * NBLK + (tid & 31)) * 32];
        while (ld_acq(f) < 1) { }
    }
    __syncthreads();

    // pre-loop: input v-build for t=0
    if (tid < CELL0) {
        if (l == 0) {
            const float4* xp = (const float4*)x;
            for (int e = tid; e < B_ * (I_ / 4); e += CELL0) {
                int b  = e / (I_ / 4);
                int k4 = e - b * (I_ / 4);
                ((float4*)(vbuf + b * KSTRIDE))[k4] =
                    xp[((size_t)b * T_) * (I_ / 4) + k4];
            }
        } else {
            const float4* ip = (const float4*)(g_hseq +
                ((size_t)((l - 1) * (T_ + 1) + 1)) * B_ * H_);
            for (int e = tid; e < B_ * (H_ / 4); e += CELL0) {
                int b  = e / (H_ / 4);
                int k4 = e - b * (H_ / 4);
                ((float4*)(vbuf + b * KSTRIDE))[k4] = ip[b * (H_ / 4) + k4];
            }
        }
    }

    for (int t = 0; t < T_; t++) {
        __syncthreads();   // S1: input-v(t) ready; own flags(t) verified

        // ---- P1: hoisted rec-v LDG + input GEMM + rec-v STS ----
        float4 rv0, rv1;
        bool rv1v = false;
        if (tid < 384) {
            const float4* hp = (const float4*)(g_hseq +
                ((size_t)(l * (T_ + 1) + t)) * B_ * H_);
            rv0 = hp[tid];                       // e = b*64 + k4, contiguous
            if (tid + 384 < B_ * (H_ / 4)) { rv1 = hp[tid + 384]; rv1v = true; }
        }
        if (in_active) {
            const float* vp0 = vbuf + kc * KCH;
            float* po = psum + (rr * B_) * PS + kc;     // input slot = kc
            #pragma unroll
            for (int pass = 0; pass < 2; pass++) {
                u64 acc[5];
                #pragma unroll
                for (int b = 0; b < 5; b++) acc[b] = 0ULL;
                const float* vp = vp0 + (size_t)(pass * 5) * KSTRIDE;
                #pragma unroll
                for (int k4 = 0; k4 < 8; k4++) {
                    const u64 w0 = wi[2 * k4];
                    const u64 w1 = wi[2 * k4 + 1];
                    #pragma unroll
                    for (int b = 0; b < 5; b++) {
                        const ulonglong2 v =
                            *(const ulonglong2*)(vp + b * KSTRIDE + k4 * 4);
                        asm("fma.rn.f32x2 %0, %1, %2, %0;"
                            : "+l"(acc[b]) : "l"(w0), "l"(v.x));
                        asm("fma.rn.f32x2 %0, %1, %2, %0;"
                            : "+l"(acc[b]) : "l"(w1), "l"(v.y));
                    }
                }
                #pragma unroll
                for (int b = 0; b < 5; b++) {
                    float xlo, xhi;
                    asm("mov.b64 {%0, %1}, %2;"
                        : "=f"(xlo), "=f"(xhi) : "l"(acc[b]));
                    po[(pass * 5 + b) * PS] = xlo + xhi;
                }
            }
        }
        if (tid < 384) {
            int b0 = tid >> 6, k40 = tid & 63;
            *(float4*)(vbuf + b0 * KSTRIDE + KIN + k40 * 4) = rv0;
            if (rv1v) {
                int e1 = tid + 384;
                int b1 = e1 >> 6, k41 = e1 & 63;
                *(float4*)(vbuf + b1 * KSTRIDE + KIN + k41 * 4) = rv1;
            }
        }
        __syncthreads();   // S2: rec-v ready; input partials in psum

        // ---- P2: recurrent GEMM (all GEMM threads) || warp12 pre-poll lower(t+2)
        if (rec_active) {
            const float* vp0 = vbuf + KIN + kc * KCH;
            float* po = psum + (rr * B_) * PS + 8 + kc;  // rec slot = 8+kc
            #pragma unroll
            for (int pass = 0; pass < 2; pass++) {
                u64 acc[5];
                #pragma unroll
                for (int b = 0; b < 5; b++) acc[b] = 0ULL;
                const float* vp = vp0 + (size_t)(pass * 5) * KSTRIDE;
                #pragma unroll
                for (int k4 = 0; k4 < 8; k4++) {
                    const u64 w0 = wr[2 * k4];
                    const u64 w1 = wr[2 * k4 + 1];
                    #pragma unroll
                    for (int b = 0; b < 5; b++) {
                        const ulonglong2 v =
                            *(const ulonglong2*)(vp + b * KSTRIDE + k4 * 4);
                        asm("fma.rn.f32x2 %0, %1, %2, %0;"
                            : "+l"(acc[b]) : "l"(w0), "l"(v.x));
                        asm("fma.rn.f32x2 %0, %1, %2, %0;"
                            : "+l"(acc[b]) : "l"(w1), "l"(v.y));
                    }
                }
                #pragma unroll
                for (int b = 0; b < 5; b++) {
                    float xlo, xhi;
                    asm("mov.b64 {%0, %1}, %2;"
                        : "=f"(xlo), "=f"(xhi) : "l"(acc[b]));
                    po[(pass * 5 + b) * PS] = xlo + xhi;
                }
            }
        } else if (wid == 12 && l > 0 && t + 2 <= T_ && (tid & 31) < NBLK) {
            const int* f = &g_prog[((l - 1) * NBLK + (tid & 31)) * 32];
            while (ld_acq(f) < t + 2) { }
        }
        __syncthreads();   // S3: all partials in psum

        // ---- P3: cell (warps 6-9) || input v-build(t+1) (warps 0-5) || own poll
        if (tid >= CELL0 && tid < CELL0 + 128) {
            const int e = tid - CELL0;
            if (e < jcB) {
                const int jl = e / B_;
                const int b  = e - jl * B_;
                float gs[4];
                #pragma unroll
                for (int gate = 0; gate < 4; gate++) {
                    const int r = gate * jc + jl;
                    const float* pp = psum + (r * B_ + b) * PS;
                    float s0 = (pp[0]  + pp[1])  + (pp[2]  + pp[3]);
                    float s1 = (pp[4]  + pp[5])  + (pp[6]  + pp[7]);
                    float s2 = (pp[8]  + pp[9])  + (pp[10] + pp[11]);
                    float s3 = (pp[12] + pp[13]) + (pp[14] + pp[15]);
                    gs[gate] = bsm[r] + ((s0 + s1) + (s2 + s3));
                }
                float ig = fmaf(0.5f, tanh_approx(0.5f * gs[0]), 0.5f);
                float fg = fmaf(0.5f, tanh_approx(0.5f * gs[1]), 0.5f);
                float gg = tanh_approx(gs[2]);
                float og = fmaf(0.5f, tanh_approx(0.5f * gs[3]), 0.5f);
                float c  = fmaf(fg, csm[e], ig * gg);
                csm[e] = c;
                float* hout = g_hseq + ((size_t)(l * (T_ + 1) + t + 1)) * B_ * H_;
                hout[(size_t)b * H_ + jbase + jl] = og * tanh_approx(c);
            }
            asm volatile("bar.sync 2, 128;" ::: "memory");
            if (tid == CELL0) {
                asm volatile("st.release.gpu.global.b32 [%0], %1;"
                             :: "l"(&g_prog[(l * NBLK + p) * 32]), "r"(t + 1));
            }
        } else if (tid < CELL0) {
            if (t + 1 < T_) {
                if (l == 0) {
                    const float4* xp = (const float4*)x;
                    for (int e = tid; e < B_ * (I_ / 4); e += CELL0) {
                        int b  = e / (I_ / 4);
                        int k4 = e - b * (I_ / 4);
                        ((float4*)(vbuf + b * KSTRIDE))[k4] =
                            xp[((size_t)b * T_ + t + 1) * (I_ / 4) + k4];
                    }
                } else {
                    const float4* ip = (const float4*)(g_hseq +
                        ((size_t)((l - 1) * (T_ + 1) + t + 2)) * B_ * H_);
                    for (int e = tid; e < B_ * (H_ / 4); e += CELL0) {
                        int b  = e / (H_ / 4);
                        int k4 = e - b * (H_ / 4);
                        ((float4*)(vbuf + b * KSTRIDE))[k4] = ip[b * (H_ / 4) + k4];
                    }
                }
            }
        } else if (wid == 13) {
            if (t + 1 < T_ && (tid & 31) < NBLK) {
                const int* f = &g_prog[(l * NBLK + (tid & 31)) * 32];
                while (ld_acq(f) < t + 1) { }
            }
        }
        // next S1 closes the stage
    }

    // ---- final cell states -> out[L][B][H] (cell threads own csm) ----
    if (tid >= CELL0 && tid < CELL0 + jcB) {
        int e  = tid - CELL0;
        int jl = e / B_;
        int b  = e - jl * B_;
        out[((size_t)l * B_ + b) * H_ + jbase + jl] = csm[e];
    }
}

extern "C" void kernel_launch(void* const* d_in, const int* in_sizes, int n_in,
                              void* d_out, int out_size) {
    const float* x    = (const float*)d_in[0];
    const float* h0   = (const float*)d_in[1];
    const float* c0   = (const float*)d_in[2];
    const float* Wih0 = (const float*)d_in[3];
    const float* Wih  = (const float*)d_in[4];
    const float* Whh  = (const float*)d_in[5];
    const float* bih  = (const float*)d_in[6];
    const float* bhh  = (const float*)d_in[7];
    float* out = (float*)d_out;

    lstm_init_kernel<<<64, 256>>>(h0);
    lstm_pipeline_kernel<<<L_ * NBLK, THREADS>>>(
        x, c0, Wih0, Wih, Whh, bih, bhh, out);
}

// round 10
// speedup vs baseline: 1.0176x; 1.0176x over previous
#include <cuda_runtime.h>
#include <math.h>

typedef unsigned long long u64;

// Problem constants
#define B_  10
#define T_  2048
#define I_  128
#define H_  256
#define L_  6
#define G4  (4 * H_)      // 1024 gate rows per layer

// Kernel config
#define NBLK     24        // blocks per layer (6*24 = 144 <= 148 SMs, co-resident)
#define THREADS  448
#define ROWS_MAX 44        // 4 * ceil(256/24)
#define JC_MAX   11
#define KC       64        // k-chunk per thread (one chunk per thread)
#define PS       9         // psum stride (8 slots + pad, conflict-free)
#define KSTRIDE  520       // vbuf row stride (floats)
#define CELL0    192       // cell threads: 192..319 (warps 6-9)

// Scratch (device globals: allocation-free contract)
__device__ float g_hseq[(size_t)L_ * (T_ + 1) * B_ * H_];
__device__ int   g_prog[L_ * NBLK * 32];   // per-block progress, 128B padded

__global__ void lstm_init_kernel(const float* __restrict__ h0) {
    int tid = blockIdx.x * blockDim.x + threadIdx.x;
    if (tid < L_ * B_ * H_) {
        int l = tid / (B_ * H_);
        int rem = tid - l * (B_ * H_);
        g_hseq[((size_t)l * (T_ + 1)) * B_ * H_ + rem] = h0[tid];
    }
    if (tid < L_ * NBLK * 32) {
        g_prog[tid] = 0;
    }
}

__device__ __forceinline__ float tanh_approx(float x) {
    float y;
    asm("tanh.approx.f32 %0, %1;" : "=f"(y) : "f"(x));
    return y;
}

__device__ __forceinline__ int ld_acq(const int* p) {
    int v;
    asm volatile("ld.acquire.gpu.global.b32 %0, [%1];" : "=r"(v) : "l"(p));
    return v;
}

// one 64-float chunk GEMM: 2 passes of 5 batches, packed f32x2 FMA
__device__ __forceinline__ void gemm_chunk(const u64* wlo, const u64* whi,
                                           const float* vp0, float* po) {
    #pragma unroll
    for (int pass = 0; pass < 2; pass++) {
        u64 acc[5];
        #pragma unroll
        for (int b = 0; b < 5; b++) acc[b] = 0ULL;
        const float* vp = vp0 + (size_t)(pass * 5) * KSTRIDE;
        #pragma unroll
        for (int k4 = 0; k4 < KC / 4; k4++) {
            const u64 w0 = wlo[k4];
            const u64 w1 = whi[k4];
            #pragma unroll
            for (int b = 0; b < 5; b++) {
                const ulonglong2 v =
                    *(const ulonglong2*)(vp + b * KSTRIDE + k4 * 4);
                asm("fma.rn.f32x2 %0, %1, %2, %0;"
                    : "+l"(acc[b]) : "l"(w0), "l"(v.x));
                asm("fma.rn.f32x2 %0, %1, %2, %0;"
                    : "+l"(acc[b]) : "l"(w1), "l"(v.y));
            }
        }
        #pragma unroll
        for (int b = 0; b < 5; b++) {
            float xlo, xhi;
            asm("mov.b64 {%0, %1}, %2;" : "=f"(xlo), "=f"(xhi) : "l"(acc[b]));
            po[(pass * 5 + b) * PS] = xlo + xhi;
        }
    }
}

__global__ void __launch_bounds__(THREADS, 1)
lstm_pipeline_kernel(const float* __restrict__ x,
                     const float* __restrict__ c0,
                     const float* __restrict__ Wih0,
                     const float* __restrict__ Wih,   // [L-1][4H][H]
                     const float* __restrict__ Whh,   // [L][4H][H]
                     const float* __restrict__ bih,   // [L][4H]
                     const float* __restrict__ bhh,   // [L][4H]
                     float* __restrict__ out)         // [L][B][H]
{
    __shared__ float vbuf[B_ * KSTRIDE];               // [input | h_prev]
    __shared__ float psum[ROWS_MAX * B_ * PS];         // partials [r][b][slot]
    __shared__ float csm[JC_MAX * B_];
    __shared__ float bsm[ROWS_MAX];

    const int l     = blockIdx.x / NBLK;
    const int p     = blockIdx.x % NBLK;
    const int jbase = (p * H_) / NBLK;
    const int jend  = ((p + 1) * H_) / NBLK;
    const int jc    = jend - jbase;     // 10 or 11
    const int rows  = 4 * jc;           // gate rows owned by this block
    const int KIN   = (l == 0) ? I_ : H_;
    const int nkcin = KIN / KC;         // input chunks: 2 or 4
    const int tid   = threadIdx.x;
    const int wid   = tid >> 5;
    const int jcB   = jc * B_;

    // ---- warp-specialized GEMM groups ----
    // A = warps 0-5 (input half), B = warps 6-11 (recurrent half)
    const bool isA = (wid < 6);
    const bool isB = (wid >= 6 && wid < 12);
    const int  idx = isA ? tid : (isB ? tid - 192 : 0);
    const int  rr  = idx % ROWS_MAX;
    const int  kk  = idx / ROWS_MAX;    // chunk index within half
    const bool gemm_on = (rr < rows) &&
        (isA ? (kk < nkcin) : (isB && idx < 4 * ROWS_MAX));
    const int  vofs = isA ? (kk * KC) : (KIN + kk * KC);
    const int  slot = isA ? kk : (nkcin + kk);

    // ---- load this thread's 64-float chunk as packed f32x2 pairs ----
    u64 wlo[KC / 4], whi[KC / 4];
    if (gemm_on) {
        const int gate = rr / jc;
        const int jl   = rr - gate * jc;
        const int g    = gate * H_ + jbase + jl;
        const float* wp;
        if (isA) {
            wp = (l == 0) ? (Wih0 + (size_t)g * I_ + kk * KC)
                          : (Wih + ((size_t)(l - 1) * G4 + g) * H_ + kk * KC);
        } else {
            wp = Whh + ((size_t)l * G4 + g) * H_ + kk * KC;
        }
        const ulonglong2* src = (const ulonglong2*)wp;
        #pragma unroll
        for (int i = 0; i < KC / 4; i++) {
            ulonglong2 w = src[i];
            wlo[i] = w.x;
            whi[i] = w.y;
        }
    } else {
        #pragma unroll
        for (int i = 0; i < KC / 4; i++) { wlo[i] = 0ULL; whi[i] = 0ULL; }
    }

    // ---- biases, initial cell state, psum zero-fill ----
    for (int r = tid; r < rows; r += THREADS) {
        int gate = r / jc;
        int jl   = r - gate * jc;
        int g    = gate * H_ + jbase + jl;
        bsm[r] = bih[l * G4 + g] + bhh[l * G4 + g];
    }
    for (int e = tid; e < jcB; e += THREADS) {
        int jl = e / B_;
        int b  = e - jl * B_;
        csm[e] = c0[((size_t)l * B_ + b) * H_ + jbase + jl];
    }
    for (int e = tid; e < ROWS_MAX * B_ * PS; e += THREADS) {
        psum[e] = 0.f;
    }
    // pre-loop: verify lower-layer flags for t=0
    if (l > 0 && wid == 12 && (tid & 31) < NBLK) {
        const int* f = &g_prog[((l - 1) * NBLK + (tid & 31)) * 32];
        while (ld_acq(f) < 1) { }
    }
    __syncthreads();

    // pre-loop: input v-build for t=0 (warps 0-5)
    if (tid < CELL0) {
        if (l == 0) {
            const float4* xp = (const float4*)x;
            for (int e = tid; e < B_ * (I_ / 4); e += CELL0) {
                int b  = e / (I_ / 4);
                int k4 = e - b * (I_ / 4);
                ((float4*)(vbuf + b * KSTRIDE))[k4] =
                    xp[((size_t)b * T_) * (I_ / 4) + k4];
            }
        } else {
            const float4* ip = (const float4*)(g_hseq +
                ((size_t)((l - 1) * (T_ + 1) + 1)) * B_ * H_);
            for (int e = tid; e < B_ * (H_ / 4); e += CELL0) {
                int b  = e / (H_ / 4);
                int k4 = e - b * (H_ / 4);
                ((float4*)(vbuf + b * KSTRIDE))[k4] = ip[b * (H_ / 4) + k4];
            }
        }
    }

    for (int t = 0; t < T_; t++) {
        __syncthreads();   // S1: input-v(t) ready; own flags(t) verified

        // ---- merged GEMM phase: A does input half; B builds rec-v then rec half
        if (isA) {
            if (gemm_on) {
                gemm_chunk(wlo, whi, vbuf + vofs, psum + (rr * B_) * PS + slot);
            }
        } else if (isB) {
            // rec-v build: LDG hseq[l][t] -> vbuf[KIN..]  (640 float4, 192 thr)
            const float4* hp = (const float4*)(g_hseq +
                ((size_t)(l * (T_ + 1) + t)) * B_ * H_);
            for (int e = tid - 192; e < B_ * (H_ / 4); e += 192) {
                int b  = e >> 6;          // H_/4 = 64
                int k4 = e & 63;
                *(float4*)(vbuf + b * KSTRIDE + KIN + k4 * 4) = hp[e];
            }
            asm volatile("bar.sync 3, 192;" ::: "memory");
            if (gemm_on) {
                gemm_chunk(wlo, whi, vbuf + vofs, psum + (rr * B_) * PS + slot);
            }
        } else if (wid == 12 && l > 0 && t + 2 <= T_ && (tid & 31) < NBLK) {
            const int* f = &g_prog[((l - 1) * NBLK + (tid & 31)) * 32];
            while (ld_acq(f) < t + 2) { }
        }
        __syncthreads();   // S3: all partials in psum

        // ---- P3: cell (warps 6-9) || input v-build(t+1) (warps 0-5) || own poll
        if (tid >= CELL0 && tid < CELL0 + 128) {
            const int e = tid - CELL0;
            if (e < jcB) {
                const int jl = e / B_;
                const int b  = e - jl * B_;
                float gs[4];
                #pragma unroll
                for (int gate = 0; gate < 4; gate++) {
                    const int r = gate * jc + jl;
                    const float* pp = psum + (r * B_ + b) * PS;
                    float s0 = pp[0] + pp[1];
                    float s1 = pp[2] + pp[3];
                    float s2 = pp[4] + pp[5];
                    float s3 = pp[6] + pp[7];
                    gs[gate] = bsm[r] + ((s0 + s1) + (s2 + s3));
                }
                float ig = fmaf(0.5f, tanh_approx(0.5f * gs[0]), 0.5f);
                float fg = fmaf(0.5f, tanh_approx(0.5f * gs[1]), 0.5f);
                float gg = tanh_approx(gs[2]);
                float og = fmaf(0.5f, tanh_approx(0.5f * gs[3]), 0.5f);
                float c  = fmaf(fg, csm[e], ig * gg);
                csm[e] = c;
                float* hout = g_hseq + ((size_t)(l * (T_ + 1) + t + 1)) * B_ * H_;
                hout[(size_t)b * H_ + jbase + jl] = og * tanh_approx(c);
            }
            asm volatile("bar.sync 2, 128;" ::: "memory");
            if (tid == CELL0) {
                asm volatile("st.release.gpu.global.b32 [%0], %1;"
                             :: "l"(&g_prog[(l * NBLK + p) * 32]), "r"(t + 1));
            }
        } else if (tid < CELL0) {
            // input v-build for t+1 (lower flags t+2 verified during GEMM phase)
            if (t + 1 < T_) {
                if (l == 0) {
                    const float4* xp = (const float4*)x;
                    for (int e = tid; e < B_ * (I_ / 4); e += CELL0) {
                        int b  = e / (I_ / 4);
                        int k4 = e - b * (I_ / 4);
                        ((float4*)(vbuf + b * KSTRIDE))[k4] =
                            xp[((size_t)b * T_ + t + 1) * (I_ / 4) + k4];
                    }
                } else {
                    const float4* ip = (const float4*)(g_hseq +
                        ((size_t)((l - 1) * (T_ + 1) + t + 2)) * B_ * H_);
                    for (int e = tid; e < B_ * (H_ / 4); e += CELL0) {
                        int b  = e / (H_ / 4);
                        int k4 = e - b * (H_ / 4);
                        ((float4*)(vbuf + b * KSTRIDE))[k4] = ip[b * (H_ / 4) + k4];
                    }
                }
            }
        } else if (wid == 13) {
            // poll own-layer flags for t+1
            if (t + 1 < T_ && (tid & 31) < NBLK) {
                const int* f = &g_prog[(l * NBLK + (tid & 31)) * 32];
                while (ld_acq(f) < t + 1) { }
            }
        }
        // next S1 closes the stage
    }

    // ---- final cell states -> out[L][B][H] (cell threads own csm) ----
    if (tid >= CELL0 && tid < CELL0 + jcB) {
        int e  = tid - CELL0;
        int jl = e / B_;
        int b  = e - jl * B_;
        out[((size_t)l * B_ + b) * H_ + jbase + jl] = csm[e];
    }
}

extern "C" void kernel_launch(void* const* d_in, const int* in_sizes, int n_in,
                              void* d_out, int out_size) {
    const float* x    = (const float*)d_in[0];
    const float* h0   = (const float*)d_in[1];
    const float* c0   = (const float*)d_in[2];
    const float* Wih0 = (const float*)d_in[3];
    const float* Wih  = (const float*)d_in[4];
    const float* Whh  = (const float*)d_in[5];
    const float* bih  = (const float*)d_in[6];
    const float* bhh  = (const float*)d_in[7];
    float* out = (float*)d_out;

    lstm_init_kernel<<<64, 256>>>(h0);
    lstm_pipeline_kernel<<<L_ * NBLK, THREADS>>>(
        x, c0, Wih0, Wih, Whh, bih, bhh, out);
}